// round 8
// baseline (speedup 1.0000x reference)
#include <cuda_runtime.h>
#include <cuda_bf16.h>

#define D 128
#define MAXN 20000
#define MAXE 640000
#define BM 64
#define BK 64

// Scratch (device globals: allocation-free per harness rules).
// float4 arrays guarantee 16B alignment for vectorized access.
__device__ float4 g_xt4[MAXN * 32];
__device__ float4 g_buf4[MAXN * 32];
__device__ int    g_deg[MAXN];
__device__ int    g_fill[MAXN];
__device__ int    g_rowptr[MAXN + 1];
__device__ float  g_deginv[MAXN];
__device__ int    g_col[MAXE];
__device__ int    g_is64;

// ---------------- edge dtype detection ----------------
// int64 edge data viewed as int32 words has all high (odd) words == 0
// (values are in [0, 20000)). int32 edge data has random odd words.
__global__ void detect_kernel(const int* __restrict__ w) {
    int acc = 0;
    #pragma unroll
    for (int i = 1; i < 64; i += 2) acc |= w[i];
    g_is64 = (acc == 0) ? 1 : 0;
}

// ---------------- CSR build ----------------

__global__ void zero_kernel(int Nn) {
    int i = blockIdx.x * blockDim.x + threadIdx.x;
    if (i < Nn) { g_deg[i] = 0; g_fill[i] = 0; }
}

__device__ __forceinline__ int clampi(int v, int n) {
    return (v < 0) ? 0 : (v >= n ? n - 1 : v);
}

__global__ void hist_kernel(const int* __restrict__ w, int E, int Nn) {
    int e = blockIdx.x * blockDim.x + threadIdx.x;
    if (e < E) {
        int d = g_is64 ? w[2 * E + 2 * e] : w[E + e];
        atomicAdd(&g_deg[clampi(d, Nn)], 1);
    }
}

__global__ __launch_bounds__(1024) void scan_kernel(int Nn) {
    __shared__ int wsum[32];
    __shared__ int sbase;
    if (threadIdx.x == 0) sbase = 0;
    __syncthreads();
    int nch = (Nn + 1023) / 1024;
    int lane = threadIdx.x & 31;
    int wrp = threadIdx.x >> 5;
    for (int c = 0; c < nch; c++) {
        int i = c * 1024 + threadIdx.x;
        int v = (i < Nn) ? g_deg[i] : 0;
        int x = v;
        #pragma unroll
        for (int o = 1; o < 32; o <<= 1) {
            int y = __shfl_up_sync(0xffffffffu, x, o);
            if (lane >= o) x += y;
        }
        if (lane == 31) wsum[wrp] = x;
        __syncthreads();
        if (threadIdx.x < 32) {
            int y = wsum[threadIdx.x];
            int z = y;
            #pragma unroll
            for (int o = 1; o < 32; o <<= 1) {
                int t = __shfl_up_sync(0xffffffffu, z, o);
                if (threadIdx.x >= o) z += t;
            }
            wsum[threadIdx.x] = z - y;   // exclusive warp offset
        }
        __syncthreads();
        int incl = x + wsum[wrp];
        int excl = incl - v;
        if (i < Nn) {
            g_rowptr[i] = sbase + excl;
            g_deginv[i] = (v > 0) ? 1.0f / (float)v : 0.0f;
        }
        __syncthreads();
        if (threadIdx.x == 1023) sbase += incl;
        __syncthreads();
    }
    if (threadIdx.x == 0) g_rowptr[Nn] = sbase;
}

__global__ void fill_kernel(const int* __restrict__ w, int E, int Nn) {
    int e = blockIdx.x * blockDim.x + threadIdx.x;
    if (e < E) {
        int is64 = g_is64;
        int d = is64 ? w[2 * E + 2 * e] : w[E + e];
        int s = is64 ? w[2 * e]         : w[e];
        d = clampi(d, Nn);
        int pos = g_rowptr[d] + atomicAdd(&g_fill[d], 1);
        g_col[pos] = clampi(s, Nn);
    }
}

// ---------------- GEMM: g_xt4 = Xin @ W^T + b ----------------
// Xin==nullptr -> read g_buf4. Always writes g_xt4.
// BM=64 rows/block, full 128 cols, BK=64 k-tile, 256 threads, 8x4 microtile.

__global__ __launch_bounds__(256) void gemm_kernel(
    const float* __restrict__ Xin, const float* __restrict__ W,
    const float* __restrict__ b, int Nn)
{
    const float* X = Xin ? Xin : (const float*)g_buf4;
    __shared__ float xs[BM][BK];
    __shared__ float wt[BK][D];   // transposed + 4-col-group swizzled
    int tid = threadIdx.x;
    int txj = tid & 31;           // col group: cols txj*4 .. +3
    int txi = tid >> 5;           // row group: rows txi*8 .. +7
    int row0 = blockIdx.x * BM;

    float acc[8][4];
    #pragma unroll
    for (int i = 0; i < 8; i++)
        #pragma unroll
        for (int j = 0; j < 4; j++) acc[i][j] = 0.f;

    for (int kt = 0; kt < D; kt += BK) {
        #pragma unroll
        for (int i = 0; i < 16; i++) {
            int idx = tid + i * 256;
            int r = idx >> 6, c = idx & 63;
            int gr = row0 + r;
            xs[r][c] = (gr < Nn) ? X[gr * D + kt + c] : 0.f;
        }
        #pragma unroll
        for (int i = 0; i < 32; i++) {
            int idx = tid + i * 256;
            int j = idx >> 6, k = idx & 63;
            int jg = ((j >> 2) + k) & 31;
            wt[k][(jg << 2) | (j & 3)] = W[j * D + kt + k];
        }
        __syncthreads();
        #pragma unroll
        for (int k = 0; k < BK; k += 4) {
            float4 xv[8];
            #pragma unroll
            for (int i = 0; i < 8; i++)
                xv[i] = *(const float4*)&xs[txi * 8 + i][k];
            #pragma unroll
            for (int kk = 0; kk < 4; kk++) {
                int jg = ((txj + (k + kk)) & 31) << 2;
                float4 wv = *(const float4*)&wt[k + kk][jg];
                #pragma unroll
                for (int i = 0; i < 8; i++) {
                    float xx = (kk == 0) ? xv[i].x : (kk == 1) ? xv[i].y
                             : (kk == 2) ? xv[i].z : xv[i].w;
                    acc[i][0] += xx * wv.x;
                    acc[i][1] += xx * wv.y;
                    acc[i][2] += xx * wv.z;
                    acc[i][3] += xx * wv.w;
                }
            }
        }
        __syncthreads();
    }
    float4 bv = *(const float4*)&b[txj * 4];
    #pragma unroll
    for (int i = 0; i < 8; i++) {
        int gr = row0 + txi * 8 + i;
        if (gr < Nn) {
            float4 o;
            o.x = acc[i][0] + bv.x;
            o.y = acc[i][1] + bv.y;
            o.z = acc[i][2] + bv.z;
            o.w = acc[i][3] + bv.w;
            g_xt4[gr * 32 + txj] = o;
        }
    }
}

// ---------------- Aggregation: out = relu(mean_in(xt[src])) + xt ----------------
// Oout==nullptr -> write g_buf4. One warp per node; lane owns one float4.

__global__ __launch_bounds__(256) void agg_kernel(float4* __restrict__ Oout, int Nn)
{
    int gw = (blockIdx.x * blockDim.x + threadIdx.x) >> 5;
    int lane = threadIdx.x & 31;
    if (gw >= Nn) return;
    float4* out = Oout ? Oout : g_buf4;
    int s = g_rowptr[gw];
    int e = g_rowptr[gw + 1];
    float4 acc = make_float4(0.f, 0.f, 0.f, 0.f);
    int i = s;
    for (; i + 4 <= e; i += 4) {
        int c0 = g_col[i], c1 = g_col[i + 1], c2 = g_col[i + 2], c3 = g_col[i + 3];
        float4 v0 = g_xt4[c0 * 32 + lane];
        float4 v1 = g_xt4[c1 * 32 + lane];
        float4 v2 = g_xt4[c2 * 32 + lane];
        float4 v3 = g_xt4[c3 * 32 + lane];
        acc.x += (v0.x + v1.x) + (v2.x + v3.x);
        acc.y += (v0.y + v1.y) + (v2.y + v3.y);
        acc.z += (v0.z + v1.z) + (v2.z + v3.z);
        acc.w += (v0.w + v1.w) + (v2.w + v3.w);
    }
    for (; i < e; i++) {
        int c = g_col[i];
        float4 v = g_xt4[c * 32 + lane];
        acc.x += v.x; acc.y += v.y; acc.z += v.z; acc.w += v.w;
    }
    float di = g_deginv[gw];
    float4 xv = g_xt4[gw * 32 + lane];
    float4 o;
    o.x = fmaxf(acc.x * di, 0.f) + xv.x;
    o.y = fmaxf(acc.y * di, 0.f) + xv.y;
    o.z = fmaxf(acc.z * di, 0.f) + xv.z;
    o.w = fmaxf(acc.w * di, 0.f) + xv.w;
    out[gw * 32 + lane] = o;
}

// ---------------- launch ----------------

extern "C" void kernel_launch(void* const* d_in, const int* in_sizes, int n_in,
                              void* d_out, int out_size)
{
    const float* x  = (const float*)d_in[0];
    const int*   ew = (const int*)d_in[1];     // edge_index words (int32 view)
    const float* W1 = (const float*)d_in[2];
    const float* b1 = (const float*)d_in[3];
    const float* W2 = (const float*)d_in[4];
    const float* b2 = (const float*)d_in[5];
    const float* W3 = (const float*)d_in[6];
    const float* b3 = (const float*)d_in[7];
    float4* out = (float4*)d_out;

    int Nn = in_sizes[0] / D;       // 20000
    int E  = in_sizes[1] / 2;       // 640000

    int gb_n = (Nn + 255) / 256;
    int gb_e = (E + 255) / 256;
    int gb_gemm = (Nn + BM - 1) / BM;
    int gb_agg = (Nn * 32 + 255) / 256;

    detect_kernel<<<1, 1>>>(ew);
    zero_kernel<<<gb_n, 256>>>(Nn);
    hist_kernel<<<gb_e, 256>>>(ew, E, Nn);
    scan_kernel<<<1, 1024>>>(Nn);
    fill_kernel<<<gb_e, 256>>>(ew, E, Nn);

    // layer 1: x -> g_xt4 -> g_buf4
    gemm_kernel<<<gb_gemm, 256>>>(x, W1, b1, Nn);
    agg_kernel<<<gb_agg, 256>>>(nullptr, Nn);
    // layer 2: g_buf4 -> g_xt4 -> g_buf4
    gemm_kernel<<<gb_gemm, 256>>>(nullptr, W2, b2, Nn);
    agg_kernel<<<gb_agg, 256>>>(nullptr, Nn);
    // layer 3: g_buf4 -> g_xt4 -> out
    gemm_kernel<<<gb_gemm, 256>>>(nullptr, W3, b3, Nn);
    agg_kernel<<<gb_agg, 256>>>(out, Nn);
}

// round 9
// speedup vs baseline: 1.1496x; 1.1496x over previous
#include <cuda_runtime.h>
#include <cuda_bf16.h>
#include <cuda_fp16.h>

#define D 128
#define MAXN 20000
#define MAXE 640000
#define BM 64
#define BK 64

// Scratch (device globals: allocation-free per harness rules).
__device__ float4 g_xt4[MAXN * 32];     // fp32 xt (residual path)
__device__ uint2  g_xth[MAXN * 32];     // fp16 mirror of xt (gather path), 4 halves/elem
__device__ float4 g_buf4[MAXN * 32];
__device__ int    g_deg[MAXN];
__device__ int    g_fill[MAXN];
__device__ int    g_rowptr[MAXN + 1];
__device__ float  g_deginv[MAXN];
__device__ int    g_col[MAXE];
__device__ int    g_bsum[32];
__device__ int    g_is64;

// ---------------- edge dtype detection ----------------
__global__ void detect_kernel(const int* __restrict__ w) {
    int acc = 0;
    #pragma unroll
    for (int i = 1; i < 64; i += 2) acc |= w[i];
    g_is64 = (acc == 0) ? 1 : 0;
}

// ---------------- CSR build ----------------

__global__ void zero_kernel(int Nn) {
    int i = blockIdx.x * blockDim.x + threadIdx.x;
    if (i < Nn) { g_deg[i] = 0; g_fill[i] = 0; }
}

__device__ __forceinline__ int clampi(int v, int n) {
    return (v < 0) ? 0 : (v >= n ? n - 1 : v);
}

__global__ void hist_kernel(const int* __restrict__ w, int E, int Nn) {
    int e = blockIdx.x * blockDim.x + threadIdx.x;
    if (e < E) {
        int d = g_is64 ? w[2 * E + 2 * e] : w[E + e];
        atomicAdd(&g_deg[clampi(d, Nn)], 1);
    }
}

// Parallel scan, pass 1: per-block (1024-wide) exclusive scan of degrees.
__global__ __launch_bounds__(1024) void scan1_kernel(int Nn) {
    __shared__ int wsum[32];
    int i = blockIdx.x * 1024 + threadIdx.x;
    int lane = threadIdx.x & 31;
    int wrp = threadIdx.x >> 5;
    int v = (i < Nn) ? g_deg[i] : 0;
    int x = v;
    #pragma unroll
    for (int o = 1; o < 32; o <<= 1) {
        int y = __shfl_up_sync(0xffffffffu, x, o);
        if (lane >= o) x += y;
    }
    if (lane == 31) wsum[wrp] = x;
    __syncthreads();
    if (threadIdx.x < 32) {
        int y = wsum[threadIdx.x];
        int z = y;
        #pragma unroll
        for (int o = 1; o < 32; o <<= 1) {
            int t = __shfl_up_sync(0xffffffffu, z, o);
            if (threadIdx.x >= o) z += t;
        }
        wsum[threadIdx.x] = z - y;   // exclusive warp offset
    }
    __syncthreads();
    int excl = x - v + wsum[wrp];
    if (i < Nn) {
        g_rowptr[i] = excl;
        g_deginv[i] = (v > 0) ? 1.0f / (float)v : 0.0f;
    }
    if (threadIdx.x == 1023) g_bsum[blockIdx.x] = excl + v;
}

// Pass 2: exclusive scan of <=32 block sums (1 warp); writes total to rowptr[Nn].
__global__ void scan2_kernel(int nb, int Nn) {
    int t = threadIdx.x;
    int v = (t < nb) ? g_bsum[t] : 0;
    int x = v;
    #pragma unroll
    for (int o = 1; o < 32; o <<= 1) {
        int y = __shfl_up_sync(0xffffffffu, x, o);
        if (t >= o) x += y;
    }
    g_bsum[t] = x - v;
    if (t == 31) g_rowptr[Nn] = x;
}

// Pass 3: add block base offsets.
__global__ void scan3_kernel(int Nn) {
    int i = blockIdx.x * blockDim.x + threadIdx.x;
    if (i < Nn) g_rowptr[i] += g_bsum[i >> 10];
}

__global__ void fill_kernel(const int* __restrict__ w, int E, int Nn) {
    int e = blockIdx.x * blockDim.x + threadIdx.x;
    if (e < E) {
        int is64 = g_is64;
        int d = is64 ? w[2 * E + 2 * e] : w[E + e];
        int s = is64 ? w[2 * e]         : w[e];
        d = clampi(d, Nn);
        int pos = g_rowptr[d] + atomicAdd(&g_fill[d], 1);
        g_col[pos] = clampi(s, Nn);
    }
}

// ---------------- GEMM: g_xt4/g_xth = Xin @ W^T + b ----------------

__global__ __launch_bounds__(256) void gemm_kernel(
    const float* __restrict__ Xin, const float* __restrict__ W,
    const float* __restrict__ b, int Nn)
{
    const float* X = Xin ? Xin : (const float*)g_buf4;
    __shared__ float xs[BM][BK];
    __shared__ float wt[BK][D];   // transposed + 4-col-group swizzled
    int tid = threadIdx.x;
    int txj = tid & 31;           // col group: cols txj*4 .. +3
    int txi = tid >> 5;           // row group: rows txi*8 .. +7
    int row0 = blockIdx.x * BM;

    float acc[8][4];
    #pragma unroll
    for (int i = 0; i < 8; i++)
        #pragma unroll
        for (int j = 0; j < 4; j++) acc[i][j] = 0.f;

    for (int kt = 0; kt < D; kt += BK) {
        #pragma unroll
        for (int i = 0; i < 16; i++) {
            int idx = tid + i * 256;
            int r = idx >> 6, c = idx & 63;
            int gr = row0 + r;
            xs[r][c] = (gr < Nn) ? X[gr * D + kt + c] : 0.f;
        }
        #pragma unroll
        for (int i = 0; i < 32; i++) {
            int idx = tid + i * 256;
            int j = idx >> 6, k = idx & 63;
            int jg = ((j >> 2) + k) & 31;
            wt[k][(jg << 2) | (j & 3)] = W[j * D + kt + k];
        }
        __syncthreads();
        #pragma unroll
        for (int k = 0; k < BK; k += 4) {
            float4 xv[8];
            #pragma unroll
            for (int i = 0; i < 8; i++)
                xv[i] = *(const float4*)&xs[txi * 8 + i][k];
            #pragma unroll
            for (int kk = 0; kk < 4; kk++) {
                int jg = ((txj + (k + kk)) & 31) << 2;
                float4 wv = *(const float4*)&wt[k + kk][jg];
                #pragma unroll
                for (int i = 0; i < 8; i++) {
                    float xx = (kk == 0) ? xv[i].x : (kk == 1) ? xv[i].y
                             : (kk == 2) ? xv[i].z : xv[i].w;
                    acc[i][0] += xx * wv.x;
                    acc[i][1] += xx * wv.y;
                    acc[i][2] += xx * wv.z;
                    acc[i][3] += xx * wv.w;
                }
            }
        }
        __syncthreads();
    }
    float4 bv = *(const float4*)&b[txj * 4];
    #pragma unroll
    for (int i = 0; i < 8; i++) {
        int gr = row0 + txi * 8 + i;
        if (gr < Nn) {
            float4 o;
            o.x = acc[i][0] + bv.x;
            o.y = acc[i][1] + bv.y;
            o.z = acc[i][2] + bv.z;
            o.w = acc[i][3] + bv.w;
            g_xt4[gr * 32 + txj] = o;
            __half2 h01 = __floats2half2_rn(o.x, o.y);
            __half2 h23 = __floats2half2_rn(o.z, o.w);
            uint2 p;
            p.x = *reinterpret_cast<unsigned*>(&h01);
            p.y = *reinterpret_cast<unsigned*>(&h23);
            g_xth[gr * 32 + txj] = p;
        }
    }
}

// ---------------- Aggregation: out = relu(mean_in(xt[src])) + xt ----------------
// Gather from fp16 mirror (half the L2 traffic), accumulate fp32,
// residual from fp32 copy. One warp per node; lane owns 4 feature cols.

__device__ __forceinline__ void acc_half4(float4& acc, uint2 p) {
    __half2 h01 = *reinterpret_cast<__half2*>(&p.x);
    __half2 h23 = *reinterpret_cast<__half2*>(&p.y);
    float2 f01 = __half22float2(h01);
    float2 f23 = __half22float2(h23);
    acc.x += f01.x; acc.y += f01.y; acc.z += f23.x; acc.w += f23.y;
}

__global__ __launch_bounds__(256) void agg_kernel(float4* __restrict__ Oout, int Nn)
{
    int gw = (blockIdx.x * blockDim.x + threadIdx.x) >> 5;
    int lane = threadIdx.x & 31;
    if (gw >= Nn) return;
    float4* out = Oout ? Oout : g_buf4;
    int s = g_rowptr[gw];
    int e = g_rowptr[gw + 1];
    float4 acc = make_float4(0.f, 0.f, 0.f, 0.f);
    int i = s;
    for (; i + 4 <= e; i += 4) {
        int c0 = g_col[i], c1 = g_col[i + 1], c2 = g_col[i + 2], c3 = g_col[i + 3];
        uint2 p0 = g_xth[c0 * 32 + lane];
        uint2 p1 = g_xth[c1 * 32 + lane];
        uint2 p2 = g_xth[c2 * 32 + lane];
        uint2 p3 = g_xth[c3 * 32 + lane];
        acc_half4(acc, p0);
        acc_half4(acc, p1);
        acc_half4(acc, p2);
        acc_half4(acc, p3);
    }
    for (; i < e; i++) {
        uint2 p = g_xth[g_col[i] * 32 + lane];
        acc_half4(acc, p);
    }
    float di = g_deginv[gw];
    float4 xv = g_xt4[gw * 32 + lane];
    float4 o;
    o.x = fmaxf(acc.x * di, 0.f) + xv.x;
    o.y = fmaxf(acc.y * di, 0.f) + xv.y;
    o.z = fmaxf(acc.z * di, 0.f) + xv.z;
    o.w = fmaxf(acc.w * di, 0.f) + xv.w;
    out[gw * 32 + lane] = o;
}

// ---------------- launch ----------------

extern "C" void kernel_launch(void* const* d_in, const int* in_sizes, int n_in,
                              void* d_out, int out_size)
{
    const float* x  = (const float*)d_in[0];
    const int*   ew = (const int*)d_in[1];     // edge_index words (int32 view)
    const float* W1 = (const float*)d_in[2];
    const float* b1 = (const float*)d_in[3];
    const float* W2 = (const float*)d_in[4];
    const float* b2 = (const float*)d_in[5];
    const float* W3 = (const float*)d_in[6];
    const float* b3 = (const float*)d_in[7];
    float4* out = (float4*)d_out;

    int Nn = in_sizes[0] / D;       // 20000
    int E  = in_sizes[1] / 2;       // 640000

    int gb_n = (Nn + 255) / 256;
    int gb_e = (E + 255) / 256;
    int gb_gemm = (Nn + BM - 1) / BM;
    int gb_agg = (Nn * 32 + 255) / 256;
    int nb_scan = (Nn + 1023) / 1024;

    detect_kernel<<<1, 1>>>(ew);
    zero_kernel<<<gb_n, 256>>>(Nn);
    hist_kernel<<<gb_e, 256>>>(ew, E, Nn);
    scan1_kernel<<<nb_scan, 1024>>>(Nn);
    scan2_kernel<<<1, 32>>>(nb_scan, Nn);
    scan3_kernel<<<gb_n, 256>>>(Nn);
    fill_kernel<<<gb_e, 256>>>(ew, E, Nn);

    // layer 1: x -> xt -> g_buf4
    gemm_kernel<<<gb_gemm, 256>>>(x, W1, b1, Nn);
    agg_kernel<<<gb_agg, 256>>>(nullptr, Nn);
    // layer 2: g_buf4 -> xt -> g_buf4
    gemm_kernel<<<gb_gemm, 256>>>(nullptr, W2, b2, Nn);
    agg_kernel<<<gb_agg, 256>>>(nullptr, Nn);
    // layer 3: g_buf4 -> xt -> out
    gemm_kernel<<<gb_gemm, 256>>>(nullptr, W3, b3, Nn);
    agg_kernel<<<gb_agg, 256>>>(out, Nn);
}

// round 10
// speedup vs baseline: 1.2097x; 1.0523x over previous
#include <cuda_runtime.h>
#include <cuda_bf16.h>
#include <cuda_fp16.h>

#define D 128
#define MAXN 20000
#define MAXE 640000
#define BM 64
#define BK 64

// Scratch (device globals: allocation-free per harness rules).
__device__ float4 g_xt4[MAXN * 32];     // fp32 xt (residual path)
__device__ uint2  g_xth[MAXN * 32];     // fp16 mirror of xt (gather path)
__device__ float4 g_buf4[MAXN * 32];
__device__ int    g_deg[MAXN];
__device__ int    g_fill[MAXN];
__device__ int    g_rowptr[MAXN + 1];
__device__ float  g_deginv[MAXN];
__device__ int    g_col[MAXE];
__device__ int    g_bsum[32];
__device__ int    g_is64;

// ---------------- packed f32x2 helpers ----------------
__device__ __forceinline__ unsigned long long pk2(float a, float b) {
    unsigned long long r;
    asm("mov.b64 %0, {%1, %2};" : "=l"(r) : "f"(a), "f"(b));
    return r;
}
__device__ __forceinline__ unsigned long long fma2(
    unsigned long long a, unsigned long long b, unsigned long long c) {
    unsigned long long d;
    asm("fma.rn.f32x2 %0, %1, %2, %3;" : "=l"(d) : "l"(a), "l"(b), "l"(c));
    return d;
}
__device__ __forceinline__ float2 up2(unsigned long long v) {
    float2 f;
    asm("mov.b64 {%0, %1}, %2;" : "=f"(f.x), "=f"(f.y) : "l"(v));
    return f;
}

// ---------------- prologue: zero + edge dtype detect ----------------
// int64 edge data viewed as int32 words has all high (odd) words == 0.
__global__ void zero_detect_kernel(const int* __restrict__ w, int Nn) {
    int i = blockIdx.x * blockDim.x + threadIdx.x;
    if (i < Nn) { g_deg[i] = 0; g_fill[i] = 0; }
    if (i == 0) {
        int acc = 0;
        #pragma unroll
        for (int j = 1; j < 64; j += 2) acc |= w[j];
        g_is64 = (acc == 0) ? 1 : 0;
    }
}

__device__ __forceinline__ int clampi(int v, int n) {
    return (v < 0) ? 0 : (v >= n ? n - 1 : v);
}

__global__ void hist_kernel(const int* __restrict__ w, int E, int Nn) {
    int e = blockIdx.x * blockDim.x + threadIdx.x;
    if (e < E) {
        int d = g_is64 ? w[2 * E + 2 * e] : w[E + e];
        atomicAdd(&g_deg[clampi(d, Nn)], 1);
    }
}

// Parallel scan, pass 1: per-block (1024-wide) exclusive scan of degrees.
__global__ __launch_bounds__(1024) void scan1_kernel(int Nn) {
    __shared__ int wsum[32];
    int i = blockIdx.x * 1024 + threadIdx.x;
    int lane = threadIdx.x & 31;
    int wrp = threadIdx.x >> 5;
    int v = (i < Nn) ? g_deg[i] : 0;
    int x = v;
    #pragma unroll
    for (int o = 1; o < 32; o <<= 1) {
        int y = __shfl_up_sync(0xffffffffu, x, o);
        if (lane >= o) x += y;
    }
    if (lane == 31) wsum[wrp] = x;
    __syncthreads();
    if (threadIdx.x < 32) {
        int y = wsum[threadIdx.x];
        int z = y;
        #pragma unroll
        for (int o = 1; o < 32; o <<= 1) {
            int t = __shfl_up_sync(0xffffffffu, z, o);
            if (threadIdx.x >= o) z += t;
        }
        wsum[threadIdx.x] = z - y;
    }
    __syncthreads();
    int excl = x - v + wsum[wrp];
    if (i < Nn) {
        g_rowptr[i] = excl;
        g_deginv[i] = (v > 0) ? 1.0f / (float)v : 0.0f;
    }
    if (threadIdx.x == 1023) g_bsum[blockIdx.x] = excl + v;
}

__global__ void scan2_kernel(int nb, int Nn) {
    int t = threadIdx.x;
    int v = (t < nb) ? g_bsum[t] : 0;
    int x = v;
    #pragma unroll
    for (int o = 1; o < 32; o <<= 1) {
        int y = __shfl_up_sync(0xffffffffu, x, o);
        if (t >= o) x += y;
    }
    g_bsum[t] = x - v;
    if (t == 31) g_rowptr[Nn] = x;
}

__global__ void scan3_kernel(int Nn) {
    int i = blockIdx.x * blockDim.x + threadIdx.x;
    if (i < Nn) g_rowptr[i] += g_bsum[i >> 10];
}

__global__ void fill_kernel(const int* __restrict__ w, int E, int Nn) {
    int e = blockIdx.x * blockDim.x + threadIdx.x;
    if (e < E) {
        int is64 = g_is64;
        int d = is64 ? w[2 * E + 2 * e] : w[E + e];
        int s = is64 ? w[2 * e]         : w[e];
        d = clampi(d, Nn);
        int pos = g_rowptr[d] + atomicAdd(&g_fill[d], 1);
        g_col[pos] = clampi(s, Nn);
    }
}

// ---------------- GEMM: g_xt4/g_xth = Xin @ W^T + b ----------------
// Packed f32x2 FMA version. X tile stored k-major with XOR swizzle so a
// single LDS.128 provides two row-pairs as register-aliased u64 operands.
// acc2[p][j]: row-pair p (rows txi*8+2p, +2p+1) x col (txj*4+j).

__global__ __launch_bounds__(256) void gemm_kernel(
    const float* __restrict__ Xin, const float* __restrict__ W,
    const float* __restrict__ b, int Nn)
{
    const float* X = Xin ? Xin : (const float*)g_buf4;
    __shared__ float xs_t[BK][BM];    // [k][row], row XOR-swizzled by (k&15)<<2
    __shared__ float wt[BK][D];       // transposed + 4-col-group swizzled
    int tid = threadIdx.x;
    int txj = tid & 31;               // col group: cols txj*4 .. +3
    int txi = tid >> 5;               // row group: rows txi*8 .. +7
    int row0 = blockIdx.x * BM;

    unsigned long long acc2[4][4];
    #pragma unroll
    for (int p = 0; p < 4; p++)
        #pragma unroll
        for (int j = 0; j < 4; j++) acc2[p][j] = 0ull;

    for (int kt = 0; kt < D; kt += BK) {
        // X tile: load row-major coalesced, store k-major swizzled
        #pragma unroll
        for (int i = 0; i < 16; i++) {
            int idx = tid + i * 256;
            int r = idx >> 6, c = idx & 63;
            int gr = row0 + r;
            float v = (gr < Nn) ? X[gr * D + kt + c] : 0.f;
            xs_t[c][r ^ ((c & 15) << 2)] = v;
        }
        // W tile: transpose W[j][k] -> wt[k][swz(j,k)]
        #pragma unroll
        for (int i = 0; i < 32; i++) {
            int idx = tid + i * 256;
            int j = idx >> 6, k = idx & 63;
            int jg = ((j >> 2) + k) & 31;
            wt[k][(jg << 2) | (j & 3)] = W[j * D + kt + k];
        }
        __syncthreads();
        #pragma unroll 16
        for (int k = 0; k < BK; k++) {
            int s = (k & 15) << 2;
            int i0 = (txi * 8) ^ s;          // quad: logical rows txi*8..+3
            float4 xa = *(const float4*)&xs_t[k][i0];
            float4 xb = *(const float4*)&xs_t[k][i0 ^ 4];  // rows txi*8+4..+7
            unsigned long long xp[4];
            xp[0] = pk2(xa.x, xa.y);
            xp[1] = pk2(xa.z, xa.w);
            xp[2] = pk2(xb.x, xb.y);
            xp[3] = pk2(xb.z, xb.w);
            int jg = ((txj + k) & 31) << 2;
            float4 wv = *(const float4*)&wt[k][jg];
            unsigned long long wj[4];
            wj[0] = pk2(wv.x, wv.x);
            wj[1] = pk2(wv.y, wv.y);
            wj[2] = pk2(wv.z, wv.z);
            wj[3] = pk2(wv.w, wv.w);
            #pragma unroll
            for (int p = 0; p < 4; p++)
                #pragma unroll
                for (int j = 0; j < 4; j++)
                    acc2[p][j] = fma2(xp[p], wj[j], acc2[p][j]);
        }
        __syncthreads();
    }
    float4 bv = *(const float4*)&b[txj * 4];
    #pragma unroll
    for (int p = 0; p < 4; p++) {
        float2 c0 = up2(acc2[p][0]);
        float2 c1 = up2(acc2[p][1]);
        float2 c2 = up2(acc2[p][2]);
        float2 c3 = up2(acc2[p][3]);
        int gr0 = row0 + txi * 8 + 2 * p;
        #pragma unroll
        for (int h = 0; h < 2; h++) {
            int gr = gr0 + h;
            if (gr < Nn) {
                float4 o;
                o.x = (h ? c0.y : c0.x) + bv.x;
                o.y = (h ? c1.y : c1.x) + bv.y;
                o.z = (h ? c2.y : c2.x) + bv.z;
                o.w = (h ? c3.y : c3.x) + bv.w;
                g_xt4[gr * 32 + txj] = o;
                __half2 h01 = __floats2half2_rn(o.x, o.y);
                __half2 h23 = __floats2half2_rn(o.z, o.w);
                uint2 pck;
                pck.x = *reinterpret_cast<unsigned*>(&h01);
                pck.y = *reinterpret_cast<unsigned*>(&h23);
                g_xth[gr * 32 + txj] = pck;
            }
        }
    }
}

// ---------------- Aggregation: out = relu(mean_in(xt[src])) + xt ----------------
// Gather fp16 mirror, accumulate fp32, residual from fp32. Warp per node,
// 8 edges in flight per iteration.

__device__ __forceinline__ void acc_half4(float4& acc, uint2 p) {
    __half2 h01 = *reinterpret_cast<__half2*>(&p.x);
    __half2 h23 = *reinterpret_cast<__half2*>(&p.y);
    float2 f01 = __half22float2(h01);
    float2 f23 = __half22float2(h23);
    acc.x += f01.x; acc.y += f01.y; acc.z += f23.x; acc.w += f23.y;
}

__global__ __launch_bounds__(256) void agg_kernel(float4* __restrict__ Oout, int Nn)
{
    int gw = (blockIdx.x * blockDim.x + threadIdx.x) >> 5;
    int lane = threadIdx.x & 31;
    if (gw >= Nn) return;
    float4* out = Oout ? Oout : g_buf4;
    int s = g_rowptr[gw];
    int e = g_rowptr[gw + 1];
    float4 acc = make_float4(0.f, 0.f, 0.f, 0.f);
    int i = s;
    for (; i + 8 <= e; i += 8) {
        int c[8];
        #pragma unroll
        for (int u = 0; u < 8; u++) c[u] = g_col[i + u];
        uint2 p[8];
        #pragma unroll
        for (int u = 0; u < 8; u++) p[u] = g_xth[c[u] * 32 + lane];
        #pragma unroll
        for (int u = 0; u < 8; u++) acc_half4(acc, p[u]);
    }
    for (; i < e; i++) {
        uint2 p = g_xth[g_col[i] * 32 + lane];
        acc_half4(acc, p);
    }
    float di = g_deginv[gw];
    float4 xv = g_xt4[gw * 32 + lane];
    float4 o;
    o.x = fmaxf(acc.x * di, 0.f) + xv.x;
    o.y = fmaxf(acc.y * di, 0.f) + xv.y;
    o.z = fmaxf(acc.z * di, 0.f) + xv.z;
    o.w = fmaxf(acc.w * di, 0.f) + xv.w;
    out[gw * 32 + lane] = o;
}

// ---------------- launch ----------------

extern "C" void kernel_launch(void* const* d_in, const int* in_sizes, int n_in,
                              void* d_out, int out_size)
{
    const float* x  = (const float*)d_in[0];
    const int*   ew = (const int*)d_in[1];     // edge_index words (int32 view)
    const float* W1 = (const float*)d_in[2];
    const float* b1 = (const float*)d_in[3];
    const float* W2 = (const float*)d_in[4];
    const float* b2 = (const float*)d_in[5];
    const float* W3 = (const float*)d_in[6];
    const float* b3 = (const float*)d_in[7];
    float4* out = (float4*)d_out;

    int Nn = in_sizes[0] / D;       // 20000
    int E  = in_sizes[1] / 2;       // 640000

    int gb_n = (Nn + 255) / 256;
    int gb_e = (E + 255) / 256;
    int gb_gemm = (Nn + BM - 1) / BM;
    int gb_agg = (Nn * 32 + 255) / 256;
    int nb_scan = (Nn + 1023) / 1024;

    zero_detect_kernel<<<gb_n, 256>>>(ew, Nn);
    hist_kernel<<<gb_e, 256>>>(ew, E, Nn);
    scan1_kernel<<<nb_scan, 1024>>>(Nn);
    scan2_kernel<<<1, 32>>>(nb_scan, Nn);
    scan3_kernel<<<gb_n, 256>>>(Nn);
    fill_kernel<<<gb_e, 256>>>(ew, E, Nn);

    // layer 1: x -> xt -> g_buf4
    gemm_kernel<<<gb_gemm, 256>>>(x, W1, b1, Nn);
    agg_kernel<<<gb_agg, 256>>>(nullptr, Nn);
    // layer 2: g_buf4 -> xt -> g_buf4
    gemm_kernel<<<gb_gemm, 256>>>(nullptr, W2, b2, Nn);
    agg_kernel<<<gb_agg, 256>>>(nullptr, Nn);
    // layer 3: g_buf4 -> xt -> out
    gemm_kernel<<<gb_gemm, 256>>>(nullptr, W3, b3, Nn);
    agg_kernel<<<gb_agg, 256>>>(out, Nn);
}

// round 11
// speedup vs baseline: 1.3715x; 1.1337x over previous
#include <cuda_runtime.h>
#include <cuda_bf16.h>
#include <cuda_fp16.h>

#define D 128
#define MAXN 20000
#define MAXE 640000
#define BM 64
#define BK 64

// Scratch (device globals: allocation-free per harness rules).
__device__ float4 g_xt4[MAXN * 32];     // fp32 xt (residual path)
__device__ uint2  g_xth[MAXN * 32];     // fp16 mirror of xt (gather path)
__device__ float4 g_buf4[MAXN * 32];
__device__ int    g_deg[MAXN];
__device__ int    g_fill[MAXN];
__device__ int    g_rowptr[MAXN + 1];
__device__ float  g_deginv[MAXN];
__device__ int    g_col[MAXE];
__device__ int    g_bsum[32];
__device__ int    g_is64;

// ---------------- prologue: zero + edge dtype detect ----------------
// int64 edge data viewed as int32 words has all high (odd) words == 0.
__global__ void zero_detect_kernel(const int* __restrict__ w, int Nn) {
    int i = blockIdx.x * blockDim.x + threadIdx.x;
    if (i < Nn) { g_deg[i] = 0; g_fill[i] = 0; }
    if (i == 0) {
        int acc = 0;
        #pragma unroll
        for (int j = 1; j < 64; j += 2) acc |= w[j];
        g_is64 = (acc == 0) ? 1 : 0;
    }
}

__device__ __forceinline__ int clampi(int v, int n) {
    return (v < 0) ? 0 : (v >= n ? n - 1 : v);
}

__global__ void hist_kernel(const int* __restrict__ w, int E, int Nn) {
    int e = blockIdx.x * blockDim.x + threadIdx.x;
    if (e < E) {
        int d = g_is64 ? w[2 * E + 2 * e] : w[E + e];
        atomicAdd(&g_deg[clampi(d, Nn)], 1);
    }
}

// Scan pass 1: per-block (1024-wide) exclusive scan of degrees.
__global__ __launch_bounds__(1024) void scan1_kernel(int Nn) {
    __shared__ int wsum[32];
    int i = blockIdx.x * 1024 + threadIdx.x;
    int lane = threadIdx.x & 31;
    int wrp = threadIdx.x >> 5;
    int v = (i < Nn) ? g_deg[i] : 0;
    int x = v;
    #pragma unroll
    for (int o = 1; o < 32; o <<= 1) {
        int y = __shfl_up_sync(0xffffffffu, x, o);
        if (lane >= o) x += y;
    }
    if (lane == 31) wsum[wrp] = x;
    __syncthreads();
    if (threadIdx.x < 32) {
        int y = wsum[threadIdx.x];
        int z = y;
        #pragma unroll
        for (int o = 1; o < 32; o <<= 1) {
            int t = __shfl_up_sync(0xffffffffu, z, o);
            if (threadIdx.x >= o) z += t;
        }
        wsum[threadIdx.x] = z - y;
    }
    __syncthreads();
    int excl = x - v + wsum[wrp];
    if (i < Nn) {
        g_rowptr[i] = excl;
        g_deginv[i] = (v > 0) ? 1.0f / (float)v : 0.0f;
    }
    if (threadIdx.x == 1023) g_bsum[blockIdx.x] = excl + v;
}

// Scan pass 2 (fused scan2+scan3): each block redundantly warp-scans the
// <=32 block sums, then adds base offsets. Block 0 writes the total.
__global__ void scan3_kernel(int nb, int Nn) {
    __shared__ int sbs[32];
    if (threadIdx.x < 32) {
        int t = threadIdx.x;
        int v = (t < nb) ? g_bsum[t] : 0;
        int x = v;
        #pragma unroll
        for (int o = 1; o < 32; o <<= 1) {
            int y = __shfl_up_sync(0xffffffffu, x, o);
            if (t >= o) x += y;
        }
        sbs[t] = x - v;
        if (blockIdx.x == 0 && t == 31) g_rowptr[Nn] = x;
    }
    __syncthreads();
    int i = blockIdx.x * blockDim.x + threadIdx.x;
    if (i < Nn) g_rowptr[i] += sbs[i >> 10];
}

__global__ void fill_kernel(const int* __restrict__ w, int E, int Nn) {
    int e = blockIdx.x * blockDim.x + threadIdx.x;
    if (e < E) {
        int is64 = g_is64;
        int d = is64 ? w[2 * E + 2 * e] : w[E + e];
        int s = is64 ? w[2 * e]         : w[e];
        d = clampi(d, Nn);
        int pos = g_rowptr[d] + atomicAdd(&g_fill[d], 1);
        g_col[pos] = clampi(s, Nn);
    }
}

// ---------------- GEMM: g_xt4/g_xth = Xin @ W^T + b ----------------
// Tensor-core mma.sync m16n8k16 bf16, hi/lo split for fp32-grade precision:
// y = Ah*Bh + Ah*Bl + Al*Bh (Al*Bl ~ 1.5e-5 rel, dropped).
// 256 threads = 8 warps; warp (wm = w&3, wn = w>>2) owns rows wm*16..+15,
// cols wn*64..+63. K=128 in two BK=64 chunks.
// SMEM word layout: row r has 32 u32 words, word w stored at w ^ ((r&7)<<2)
// -> conflict-free for both the conversion STS and the fragment LDS pattern.

__device__ __forceinline__ unsigned pack_bf16_hi(float2 v, float2& rem) {
    __nv_bfloat16 h0 = __float2bfloat16_rn(v.x);
    __nv_bfloat16 h1 = __float2bfloat16_rn(v.y);
    rem.x = v.x - __bfloat162float(h0);
    rem.y = v.y - __bfloat162float(h1);
    __nv_bfloat162 p = __nv_bfloat162(h0, h1);
    return *reinterpret_cast<unsigned*>(&p);
}
__device__ __forceinline__ unsigned pack_bf16(float2 v) {
    __nv_bfloat162 p = __nv_bfloat162(__float2bfloat16_rn(v.x), __float2bfloat16_rn(v.y));
    return *reinterpret_cast<unsigned*>(&p);
}

__device__ __forceinline__ void mma_bf16(
    float* c, unsigned a0, unsigned a1, unsigned a2, unsigned a3,
    unsigned b0, unsigned b1)
{
    asm volatile(
        "mma.sync.aligned.m16n8k16.row.col.f32.bf16.bf16.f32 "
        "{%0,%1,%2,%3}, {%4,%5,%6,%7}, {%8,%9}, {%0,%1,%2,%3};"
        : "+f"(c[0]), "+f"(c[1]), "+f"(c[2]), "+f"(c[3])
        : "r"(a0), "r"(a1), "r"(a2), "r"(a3), "r"(b0), "r"(b1));
}

__device__ __forceinline__ int swz(int r, int w) { return r * 32 + (w ^ ((r & 7) << 2)); }

__global__ __launch_bounds__(256) void gemm_kernel(
    const float* __restrict__ Xin, const float* __restrict__ W,
    const float* __restrict__ b, int Nn)
{
    const float* X = Xin ? Xin : (const float*)g_buf4;
    __shared__ unsigned sAh[64 * 32];
    __shared__ unsigned sAl[64 * 32];
    __shared__ unsigned sWh[128 * 32];
    __shared__ unsigned sWl[128 * 32];

    int tid = threadIdx.x;
    int lane = tid & 31;
    int wrp = tid >> 5;
    int wm = wrp & 3;                 // rows wm*16 .. +15
    int wn = wrp >> 2;                // cols wn*64 .. +63
    int g = lane >> 2;                // 0..7
    int tq = lane & 3;                // 0..3
    int row0 = blockIdx.x * BM;

    float c[8][4];
    #pragma unroll
    for (int j = 0; j < 8; j++)
        #pragma unroll
        for (int q = 0; q < 4; q++) c[j][q] = 0.f;

    for (int kt = 0; kt < D; kt += BK) {
        if (kt) __syncthreads();      // protect SMEM reuse across chunks
        // Convert X tile: 64 rows x 32 words
        #pragma unroll
        for (int i = 0; i < 8; i++) {
            int idx = tid + i * 256;
            int r = idx >> 5, w = idx & 31;
            int gr = row0 + r;
            float2 v = (gr < Nn) ? *(const float2*)&X[gr * D + kt + 2 * w]
                                 : make_float2(0.f, 0.f);
            float2 rem;
            sAh[swz(r, w)] = pack_bf16_hi(v, rem);
            sAl[swz(r, w)] = pack_bf16(rem);
        }
        // Convert W tile: 128 rows x 32 words
        #pragma unroll
        for (int i = 0; i < 16; i++) {
            int idx = tid + i * 256;
            int r = idx >> 5, w = idx & 31;
            float2 v = *(const float2*)&W[r * D + kt + 2 * w];
            float2 rem;
            sWh[swz(r, w)] = pack_bf16_hi(v, rem);
            sWl[swz(r, w)] = pack_bf16(rem);
        }
        __syncthreads();

        #pragma unroll
        for (int ks = 0; ks < 4; ks++) {
            int ra = wm * 16 + g;
            int wa = ks * 8 + tq;
            unsigned ah0 = sAh[swz(ra, wa)];
            unsigned ah1 = sAh[swz(ra + 8, wa)];
            unsigned ah2 = sAh[swz(ra, wa + 4)];
            unsigned ah3 = sAh[swz(ra + 8, wa + 4)];
            unsigned al0 = sAl[swz(ra, wa)];
            unsigned al1 = sAl[swz(ra + 8, wa)];
            unsigned al2 = sAl[swz(ra, wa + 4)];
            unsigned al3 = sAl[swz(ra + 8, wa + 4)];
            #pragma unroll
            for (int j = 0; j < 8; j++) {
                int rb = wn * 64 + j * 8 + g;
                unsigned bh0 = sWh[swz(rb, wa)];
                unsigned bh1 = sWh[swz(rb, wa + 4)];
                unsigned bl0 = sWl[swz(rb, wa)];
                unsigned bl1 = sWl[swz(rb, wa + 4)];
                mma_bf16(c[j], ah0, ah1, ah2, ah3, bh0, bh1);
                mma_bf16(c[j], ah0, ah1, ah2, ah3, bl0, bl1);
                mma_bf16(c[j], al0, al1, al2, al3, bh0, bh1);
            }
        }
    }

    // Epilogue: bias add, fp32 store + fp16 mirror.
    float* xtf = (float*)g_xt4;
    __half2* xth2 = (__half2*)g_xth;
    int r0a = row0 + wm * 16 + g;
    #pragma unroll
    for (int j = 0; j < 8; j++) {
        int cn = wn * 64 + j * 8 + 2 * tq;
        float bx = b[cn], by = b[cn + 1];
        float2 lo = make_float2(c[j][0] + bx, c[j][1] + by);
        float2 hi = make_float2(c[j][2] + bx, c[j][3] + by);
        if (r0a < Nn) {
            *(float2*)&xtf[r0a * D + cn] = lo;
            xth2[r0a * 64 + cn / 2] = __floats2half2_rn(lo.x, lo.y);
        }
        if (r0a + 8 < Nn) {
            *(float2*)&xtf[(r0a + 8) * D + cn] = hi;
            xth2[(r0a + 8) * 64 + cn / 2] = __floats2half2_rn(hi.x, hi.y);
        }
    }
}

// ---------------- Aggregation: out = relu(mean_in(xt[src])) + xt ----------------
// Gather fp16 mirror, accumulate fp32, residual from fp32. Warp per node,
// 16 edges in flight per iteration.

__device__ __forceinline__ void acc_half4(float4& acc, uint2 p) {
    __half2 h01 = *reinterpret_cast<__half2*>(&p.x);
    __half2 h23 = *reinterpret_cast<__half2*>(&p.y);
    float2 f01 = __half22float2(h01);
    float2 f23 = __half22float2(h23);
    acc.x += f01.x; acc.y += f01.y; acc.z += f23.x; acc.w += f23.y;
}

__global__ __launch_bounds__(256) void agg_kernel(float4* __restrict__ Oout, int Nn)
{
    int gw = (blockIdx.x * blockDim.x + threadIdx.x) >> 5;
    int lane = threadIdx.x & 31;
    if (gw >= Nn) return;
    float4* out = Oout ? Oout : g_buf4;
    int s = g_rowptr[gw];
    int e = g_rowptr[gw + 1];
    float4 acc = make_float4(0.f, 0.f, 0.f, 0.f);
    int i = s;
    for (; i + 16 <= e; i += 16) {
        int cdx[16];
        #pragma unroll
        for (int u = 0; u < 16; u++) cdx[u] = g_col[i + u];
        uint2 p[16];
        #pragma unroll
        for (int u = 0; u < 16; u++) p[u] = g_xth[cdx[u] * 32 + lane];
        #pragma unroll
        for (int u = 0; u < 16; u++) acc_half4(acc, p[u]);
    }
    for (; i + 4 <= e; i += 4) {
        int c0 = g_col[i], c1 = g_col[i + 1], c2 = g_col[i + 2], c3 = g_col[i + 3];
        uint2 p0 = g_xth[c0 * 32 + lane];
        uint2 p1 = g_xth[c1 * 32 + lane];
        uint2 p2 = g_xth[c2 * 32 + lane];
        uint2 p3 = g_xth[c3 * 32 + lane];
        acc_half4(acc, p0); acc_half4(acc, p1);
        acc_half4(acc, p2); acc_half4(acc, p3);
    }
    for (; i < e; i++) {
        uint2 p = g_xth[g_col[i] * 32 + lane];
        acc_half4(acc, p);
    }
    float di = g_deginv[gw];
    float4 xv = g_xt4[gw * 32 + lane];
    float4 o;
    o.x = fmaxf(acc.x * di, 0.f) + xv.x;
    o.y = fmaxf(acc.y * di, 0.f) + xv.y;
    o.z = fmaxf(acc.z * di, 0.f) + xv.z;
    o.w = fmaxf(acc.w * di, 0.f) + xv.w;
    out[gw * 32 + lane] = o;
}

// ---------------- launch ----------------

extern "C" void kernel_launch(void* const* d_in, const int* in_sizes, int n_in,
                              void* d_out, int out_size)
{
    const float* x  = (const float*)d_in[0];
    const int*   ew = (const int*)d_in[1];     // edge_index words (int32 view)
    const float* W1 = (const float*)d_in[2];
    const float* b1 = (const float*)d_in[3];
    const float* W2 = (const float*)d_in[4];
    const float* b2 = (const float*)d_in[5];
    const float* W3 = (const float*)d_in[6];
    const float* b3 = (const float*)d_in[7];
    float4* out = (float4*)d_out;

    int Nn = in_sizes[0] / D;       // 20000
    int E  = in_sizes[1] / 2;       // 640000

    int gb_n = (Nn + 255) / 256;
    int gb_e = (E + 255) / 256;
    int gb_gemm = (Nn + BM - 1) / BM;
    int gb_agg = (Nn * 32 + 255) / 256;
    int nb_scan = (Nn + 1023) / 1024;

    zero_detect_kernel<<<gb_n, 256>>>(ew, Nn);
    hist_kernel<<<gb_e, 256>>>(ew, E, Nn);
    scan1_kernel<<<nb_scan, 1024>>>(Nn);
    scan3_kernel<<<gb_n, 256>>>(nb_scan, Nn);
    fill_kernel<<<gb_e, 256>>>(ew, E, Nn);

    // layer 1: x -> xt -> g_buf4
    gemm_kernel<<<gb_gemm, 256>>>(x, W1, b1, Nn);
    agg_kernel<<<gb_agg, 256>>>(nullptr, Nn);
    // layer 2: g_buf4 -> xt -> g_buf4
    gemm_kernel<<<gb_gemm, 256>>>(nullptr, W2, b2, Nn);
    agg_kernel<<<gb_agg, 256>>>(nullptr, Nn);
    // layer 3: g_buf4 -> xt -> out
    gemm_kernel<<<gb_gemm, 256>>>(nullptr, W3, b3, Nn);
    agg_kernel<<<gb_agg, 256>>>(out, Nn);
}

// round 12
// speedup vs baseline: 1.4627x; 1.0665x over previous
#include <cuda_runtime.h>
#include <cuda_bf16.h>
#include <cuda_fp16.h>

#define D 128
#define MAXN 20000
#define MAXE 640000
#define BM 64
#define BK 64

// Scratch (device globals: allocation-free per harness rules).
// Invariant: g_deg/g_fill are all-zero at kernel_launch entry; scan1 restores
// this every launch (reads then zeroes), so graph replays stay deterministic.
__device__ float4 g_xt4[MAXN * 32];     // fp32 xt (residual path)
__device__ uint2  g_xth[MAXN * 32];     // fp16 mirror of xt (gather path)
__device__ float4 g_buf4[MAXN * 32];
__device__ int    g_deg[MAXN];
__device__ int    g_fill[MAXN];
__device__ int    g_rowptr[MAXN + 1];
__device__ float  g_deginv[MAXN];
__device__ int    g_col[MAXE];
__device__ int    g_bsum[32];

__device__ __forceinline__ int clampi(int v, int n) {
    return (v < 0) ? 0 : (v >= n ? n - 1 : v);
}

// Per-block edge dtype detect: int64 data viewed as int32 has all odd words 0.
__device__ __forceinline__ int detect_is64(const int* __restrict__ w) {
    __shared__ int s64;
    if (threadIdx.x == 0) {
        int acc = 0;
        #pragma unroll
        for (int j = 1; j < 64; j += 2) acc |= w[j];
        s64 = (acc == 0) ? 1 : 0;
    }
    __syncthreads();
    return s64;
}

// ---------------- CSR build ----------------

__global__ void hist_kernel(const int* __restrict__ w, int E, int Nn) {
    int is64 = detect_is64(w);
    int e = blockIdx.x * blockDim.x + threadIdx.x;
    if (e < E) {
        int d = is64 ? w[2 * E + 2 * e] : w[E + e];
        atomicAdd(&g_deg[clampi(d, Nn)], 1);
    }
}

// Scan pass 1: per-block (1024-wide) exclusive scan of degrees.
// Also zeroes g_deg (restores invariant for next launch) and g_fill
// (needed zero before fill_kernel later this launch).
__global__ __launch_bounds__(1024) void scan1_kernel(int Nn) {
    __shared__ int wsum[32];
    int i = blockIdx.x * 1024 + threadIdx.x;
    int lane = threadIdx.x & 31;
    int wrp = threadIdx.x >> 5;
    int v = 0;
    if (i < Nn) {
        v = g_deg[i];
        g_deg[i] = 0;
        g_fill[i] = 0;
    }
    int x = v;
    #pragma unroll
    for (int o = 1; o < 32; o <<= 1) {
        int y = __shfl_up_sync(0xffffffffu, x, o);
        if (lane >= o) x += y;
    }
    if (lane == 31) wsum[wrp] = x;
    __syncthreads();
    if (threadIdx.x < 32) {
        int y = wsum[threadIdx.x];
        int z = y;
        #pragma unroll
        for (int o = 1; o < 32; o <<= 1) {
            int t = __shfl_up_sync(0xffffffffu, z, o);
            if (threadIdx.x >= o) z += t;
        }
        wsum[threadIdx.x] = z - y;
    }
    __syncthreads();
    int excl = x - v + wsum[wrp];
    if (i < Nn) {
        g_rowptr[i] = excl;
        g_deginv[i] = (v > 0) ? 1.0f / (float)v : 0.0f;
    }
    if (threadIdx.x == 1023) g_bsum[blockIdx.x] = excl + v;
}

// Scan pass 2: each block redundantly warp-scans the <=32 block sums,
// then adds base offsets. Block 0 writes the total.
__global__ __launch_bounds__(1024) void scan3_kernel(int nb, int Nn) {
    __shared__ int sbs[32];
    if (threadIdx.x < 32) {
        int t = threadIdx.x;
        int v = (t < nb) ? g_bsum[t] : 0;
        int x = v;
        #pragma unroll
        for (int o = 1; o < 32; o <<= 1) {
            int y = __shfl_up_sync(0xffffffffu, x, o);
            if (t >= o) x += y;
        }
        sbs[t] = x - v;
        if (blockIdx.x == 0 && t == 31) g_rowptr[Nn] = x;
    }
    __syncthreads();
    int i = blockIdx.x * blockDim.x + threadIdx.x;
    if (i < Nn) g_rowptr[i] += sbs[i >> 10];
}

__global__ void fill_kernel(const int* __restrict__ w, int E, int Nn) {
    int is64 = detect_is64(w);
    int e = blockIdx.x * blockDim.x + threadIdx.x;
    if (e < E) {
        int d = is64 ? w[2 * E + 2 * e] : w[E + e];
        int s = is64 ? w[2 * e]         : w[e];
        d = clampi(d, Nn);
        int pos = g_rowptr[d] + atomicAdd(&g_fill[d], 1);
        g_col[pos] = clampi(s, Nn);
    }
}

// ---------------- GEMM: g_xt4/g_xth = Xin @ W^T + b ----------------
// Tensor-core mma.sync m16n8k16 bf16, hi/lo split: y = Ah*Bh + Ah*Bl + Al*Bh.

__device__ __forceinline__ unsigned pack_bf16_hi(float2 v, float2& rem) {
    __nv_bfloat16 h0 = __float2bfloat16_rn(v.x);
    __nv_bfloat16 h1 = __float2bfloat16_rn(v.y);
    rem.x = v.x - __bfloat162float(h0);
    rem.y = v.y - __bfloat162float(h1);
    __nv_bfloat162 p = __nv_bfloat162(h0, h1);
    return *reinterpret_cast<unsigned*>(&p);
}
__device__ __forceinline__ unsigned pack_bf16(float2 v) {
    __nv_bfloat162 p = __nv_bfloat162(__float2bfloat16_rn(v.x), __float2bfloat16_rn(v.y));
    return *reinterpret_cast<unsigned*>(&p);
}

__device__ __forceinline__ void mma_bf16(
    float* c, unsigned a0, unsigned a1, unsigned a2, unsigned a3,
    unsigned b0, unsigned b1)
{
    asm volatile(
        "mma.sync.aligned.m16n8k16.row.col.f32.bf16.bf16.f32 "
        "{%0,%1,%2,%3}, {%4,%5,%6,%7}, {%8,%9}, {%0,%1,%2,%3};"
        : "+f"(c[0]), "+f"(c[1]), "+f"(c[2]), "+f"(c[3])
        : "r"(a0), "r"(a1), "r"(a2), "r"(a3), "r"(b0), "r"(b1));
}

__device__ __forceinline__ int swz(int r, int w) { return r * 32 + (w ^ ((r & 7) << 2)); }

__global__ __launch_bounds__(256) void gemm_kernel(
    const float* __restrict__ Xin, const float* __restrict__ W,
    const float* __restrict__ b, int Nn)
{
    const float* X = Xin ? Xin : (const float*)g_buf4;
    __shared__ unsigned sAh[64 * 32];
    __shared__ unsigned sAl[64 * 32];
    __shared__ unsigned sWh[128 * 32];
    __shared__ unsigned sWl[128 * 32];

    int tid = threadIdx.x;
    int lane = tid & 31;
    int wrp = tid >> 5;
    int wm = wrp & 3;
    int wn = wrp >> 2;
    int g = lane >> 2;
    int tq = lane & 3;
    int row0 = blockIdx.x * BM;

    float c[8][4];
    #pragma unroll
    for (int j = 0; j < 8; j++)
        #pragma unroll
        for (int q = 0; q < 4; q++) c[j][q] = 0.f;

    for (int kt = 0; kt < D; kt += BK) {
        if (kt) __syncthreads();
        #pragma unroll
        for (int i = 0; i < 8; i++) {
            int idx = tid + i * 256;
            int r = idx >> 5, w = idx & 31;
            int gr = row0 + r;
            float2 v = (gr < Nn) ? *(const float2*)&X[gr * D + kt + 2 * w]
                                 : make_float2(0.f, 0.f);
            float2 rem;
            sAh[swz(r, w)] = pack_bf16_hi(v, rem);
            sAl[swz(r, w)] = pack_bf16(rem);
        }
        #pragma unroll
        for (int i = 0; i < 16; i++) {
            int idx = tid + i * 256;
            int r = idx >> 5, w = idx & 31;
            float2 v = *(const float2*)&W[r * D + kt + 2 * w];
            float2 rem;
            sWh[swz(r, w)] = pack_bf16_hi(v, rem);
            sWl[swz(r, w)] = pack_bf16(rem);
        }
        __syncthreads();

        #pragma unroll
        for (int ks = 0; ks < 4; ks++) {
            int ra = wm * 16 + g;
            int wa = ks * 8 + tq;
            unsigned ah0 = sAh[swz(ra, wa)];
            unsigned ah1 = sAh[swz(ra + 8, wa)];
            unsigned ah2 = sAh[swz(ra, wa + 4)];
            unsigned ah3 = sAh[swz(ra + 8, wa + 4)];
            unsigned al0 = sAl[swz(ra, wa)];
            unsigned al1 = sAl[swz(ra + 8, wa)];
            unsigned al2 = sAl[swz(ra, wa + 4)];
            unsigned al3 = sAl[swz(ra + 8, wa + 4)];
            #pragma unroll
            for (int j = 0; j < 8; j++) {
                int rb = wn * 64 + j * 8 + g;
                unsigned bh0 = sWh[swz(rb, wa)];
                unsigned bh1 = sWh[swz(rb, wa + 4)];
                unsigned bl0 = sWl[swz(rb, wa)];
                unsigned bl1 = sWl[swz(rb, wa + 4)];
                mma_bf16(c[j], ah0, ah1, ah2, ah3, bh0, bh1);
                mma_bf16(c[j], ah0, ah1, ah2, ah3, bl0, bl1);
                mma_bf16(c[j], al0, al1, al2, al3, bh0, bh1);
            }
        }
    }

    float* xtf = (float*)g_xt4;
    __half2* xth2 = (__half2*)g_xth;
    int r0a = row0 + wm * 16 + g;
    #pragma unroll
    for (int j = 0; j < 8; j++) {
        int cn = wn * 64 + j * 8 + 2 * tq;
        float bx = b[cn], by = b[cn + 1];
        float2 lo = make_float2(c[j][0] + bx, c[j][1] + by);
        float2 hi = make_float2(c[j][2] + bx, c[j][3] + by);
        if (r0a < Nn) {
            *(float2*)&xtf[r0a * D + cn] = lo;
            xth2[r0a * 64 + cn / 2] = __floats2half2_rn(lo.x, lo.y);
        }
        if (r0a + 8 < Nn) {
            *(float2*)&xtf[(r0a + 8) * D + cn] = hi;
            xth2[(r0a + 8) * 64 + cn / 2] = __floats2half2_rn(hi.x, hi.y);
        }
    }
}

// ---------------- Aggregation: out = relu(mean_in(xt[src])) + xt ----------------
// Gather fp16 mirror; accumulate pairs in fp16 (HADD2), flush to fp32 every
// 8 edges. Warp per node, 8 loads in flight.

__device__ __forceinline__ void acc_half4(float4& acc, uint2 p) {
    __half2 h01 = *reinterpret_cast<__half2*>(&p.x);
    __half2 h23 = *reinterpret_cast<__half2*>(&p.y);
    float2 f01 = __half22float2(h01);
    float2 f23 = __half22float2(h23);
    acc.x += f01.x; acc.y += f01.y; acc.z += f23.x; acc.w += f23.y;
}

__global__ __launch_bounds__(256) void agg_kernel(float4* __restrict__ Oout, int Nn)
{
    int gw = (blockIdx.x * blockDim.x + threadIdx.x) >> 5;
    int lane = threadIdx.x & 31;
    if (gw >= Nn) return;
    float4* out = Oout ? Oout : g_buf4;
    int s = g_rowptr[gw];
    int e = g_rowptr[gw + 1];
    float4 acc = make_float4(0.f, 0.f, 0.f, 0.f);
    int i = s;
    for (; i + 8 <= e; i += 8) {
        uint2 p[8];
        #pragma unroll
        for (int u = 0; u < 8; u++) p[u] = g_xth[g_col[i + u] * 32 + lane];
        __half2 h01 = __float2half2_rn(0.f);
        __half2 h23 = __float2half2_rn(0.f);
        #pragma unroll
        for (int u = 0; u < 8; u++) {
            h01 = __hadd2(h01, *reinterpret_cast<__half2*>(&p[u].x));
            h23 = __hadd2(h23, *reinterpret_cast<__half2*>(&p[u].y));
        }
        float2 f01 = __half22float2(h01);
        float2 f23 = __half22float2(h23);
        acc.x += f01.x; acc.y += f01.y; acc.z += f23.x; acc.w += f23.y;
    }
    for (; i < e; i++) {
        uint2 p = g_xth[g_col[i] * 32 + lane];
        acc_half4(acc, p);
    }
    float di = g_deginv[gw];
    float4 xv = g_xt4[gw * 32 + lane];
    float4 o;
    o.x = fmaxf(acc.x * di, 0.f) + xv.x;
    o.y = fmaxf(acc.y * di, 0.f) + xv.y;
    o.z = fmaxf(acc.z * di, 0.f) + xv.z;
    o.w = fmaxf(acc.w * di, 0.f) + xv.w;
    out[gw * 32 + lane] = o;
}

// ---------------- launch ----------------

extern "C" void kernel_launch(void* const* d_in, const int* in_sizes, int n_in,
                              void* d_out, int out_size)
{
    const float* x  = (const float*)d_in[0];
    const int*   ew = (const int*)d_in[1];     // edge_index words (int32 view)
    const float* W1 = (const float*)d_in[2];
    const float* b1 = (const float*)d_in[3];
    const float* W2 = (const float*)d_in[4];
    const float* b2 = (const float*)d_in[5];
    const float* W3 = (const float*)d_in[6];
    const float* b3 = (const float*)d_in[7];
    float4* out = (float4*)d_out;

    int Nn = in_sizes[0] / D;       // 20000
    int E  = in_sizes[1] / 2;       // 640000

    int gb_e = (E + 255) / 256;
    int gb_gemm = (Nn + BM - 1) / BM;
    int gb_agg = (Nn * 32 + 255) / 256;
    int nb_scan = (Nn + 1023) / 1024;

    hist_kernel<<<gb_e, 256>>>(ew, E, Nn);
    scan1_kernel<<<nb_scan, 1024>>>(Nn);
    scan3_kernel<<<nb_scan, 1024>>>(nb_scan, Nn);
    fill_kernel<<<gb_e, 256>>>(ew, E, Nn);

    // layer 1: x -> xt -> g_buf4
    gemm_kernel<<<gb_gemm, 256>>>(x, W1, b1, Nn);
    agg_kernel<<<gb_agg, 256>>>(nullptr, Nn);
    // layer 2: g_buf4 -> xt -> g_buf4
    gemm_kernel<<<gb_gemm, 256>>>(nullptr, W2, b2, Nn);
    agg_kernel<<<gb_agg, 256>>>(nullptr, Nn);
    // layer 3: g_buf4 -> xt -> out
    gemm_kernel<<<gb_gemm, 256>>>(nullptr, W3, b3, Nn);
    agg_kernel<<<gb_agg, 256>>>(out, Nn);
}

// round 13
// speedup vs baseline: 1.5445x; 1.0559x over previous
#include <cuda_runtime.h>
#include <cuda_bf16.h>
#include <cuda_fp16.h>

#define D 128
#define MAXN 20000
#define MAXE 640000
#define BM 64
#define BK 64

// Scratch (device globals: allocation-free per harness rules).
// Invariant: g_deg is all-zero at kernel_launch entry; scan1 restores this
// every launch (reads then zeroes), so graph replays stay deterministic.
__device__ float4   g_xt4[MAXN * 32];   // fp32 xt (residual path)
__device__ uint2    g_xth[MAXN * 32];   // fp16 mirror of xt (gather path)
__device__ float4   g_buf4[MAXN * 32];
__device__ int      g_deg[MAXN];
__device__ int      g_rowptr[MAXN + 1];
__device__ float    g_deginv[MAXN];
__device__ int      g_col[MAXE];
__device__ int      g_rank[MAXE];
__device__ int      g_bsum[32];
__device__ unsigned g_Wh[3][128 * 64];  // W bf16-hi words (2 bf16/word, k-pairs)
__device__ unsigned g_Wl[3][128 * 64];  // W bf16-lo (residual) words

__device__ __forceinline__ int clampi(int v, int n) {
    return (v < 0) ? 0 : (v >= n ? n - 1 : v);
}

// Per-block edge dtype detect: int64 data viewed as int32 has all odd words 0.
__device__ __forceinline__ int detect_is64(const int* __restrict__ w) {
    __shared__ int s64;
    if (threadIdx.x == 0) {
        int acc = 0;
        #pragma unroll
        for (int j = 1; j < 64; j += 2) acc |= w[j];
        s64 = (acc == 0) ? 1 : 0;
    }
    __syncthreads();
    return s64;
}

// ---------------- CSR build ----------------
// hist: degree histogram; atomicAdd's return value IS the edge's rank within
// its destination bucket -> saved to g_rank, so fill needs no atomic.

__global__ void hist_kernel(const int* __restrict__ w, int E, int Nn) {
    int is64 = detect_is64(w);
    int idx = blockIdx.x * blockDim.x + threadIdx.x;
    int e0 = 2 * idx;
    if (e0 >= E) return;
    int d0, d1 = -1;
    if (is64) {
        const int4* dst4 = (const int4*)(w + 2 * E);
        int4 v = dst4[idx];
        d0 = v.x;
        if (e0 + 1 < E) d1 = v.z;
    } else {
        const int2* dst2 = (const int2*)(w + E);
        int2 v = dst2[idx];
        d0 = v.x;
        if (e0 + 1 < E) d1 = v.y;
    }
    int r0 = atomicAdd(&g_deg[clampi(d0, Nn)], 1);
    if (d1 >= 0 || (e0 + 1 < E)) {
        int r1 = atomicAdd(&g_deg[clampi(d1, Nn)], 1);
        *(int2*)&g_rank[e0] = make_int2(r0, r1);
    } else {
        g_rank[e0] = r0;
    }
}

// Scan pass 1: per-block (1024-wide) exclusive scan of degrees.
// Zeroes g_deg afterward (restores invariant for next graph replay).
__global__ __launch_bounds__(1024) void scan1_kernel(int Nn) {
    __shared__ int wsum[32];
    int i = blockIdx.x * 1024 + threadIdx.x;
    int lane = threadIdx.x & 31;
    int wrp = threadIdx.x >> 5;
    int v = 0;
    if (i < Nn) {
        v = g_deg[i];
        g_deg[i] = 0;
    }
    int x = v;
    #pragma unroll
    for (int o = 1; o < 32; o <<= 1) {
        int y = __shfl_up_sync(0xffffffffu, x, o);
        if (lane >= o) x += y;
    }
    if (lane == 31) wsum[wrp] = x;
    __syncthreads();
    if (threadIdx.x < 32) {
        int y = wsum[threadIdx.x];
        int z = y;
        #pragma unroll
        for (int o = 1; o < 32; o <<= 1) {
            int t = __shfl_up_sync(0xffffffffu, z, o);
            if (threadIdx.x >= o) z += t;
        }
        wsum[threadIdx.x] = z - y;
    }
    __syncthreads();
    int excl = x - v + wsum[wrp];
    if (i < Nn) {
        g_rowptr[i] = excl;
        g_deginv[i] = (v > 0) ? 1.0f / (float)v : 0.0f;
    }
    if (threadIdx.x == 1023) g_bsum[blockIdx.x] = excl + v;
}

// Scan pass 2: each block redundantly warp-scans the <=32 block sums,
// then adds base offsets. Block 0 writes the total.
__global__ __launch_bounds__(1024) void scan3_kernel(int nb, int Nn) {
    __shared__ int sbs[32];
    if (threadIdx.x < 32) {
        int t = threadIdx.x;
        int v = (t < nb) ? g_bsum[t] : 0;
        int x = v;
        #pragma unroll
        for (int o = 1; o < 32; o <<= 1) {
            int y = __shfl_up_sync(0xffffffffu, x, o);
            if (t >= o) x += y;
        }
        sbs[t] = x - v;
        if (blockIdx.x == 0 && t == 31) g_rowptr[Nn] = x;
    }
    __syncthreads();
    int i = blockIdx.x * blockDim.x + threadIdx.x;
    if (i < Nn) g_rowptr[i] += sbs[i >> 10];
}

// fill: no atomics — position = rowptr[dst] + rank[e].
__global__ void fill_kernel(const int* __restrict__ w, int E, int Nn) {
    int is64 = detect_is64(w);
    int idx = blockIdx.x * blockDim.x + threadIdx.x;
    int e0 = 2 * idx;
    if (e0 >= E) return;
    int s0, d0, s1 = 0, d1 = 0;
    bool two = (e0 + 1 < E);
    if (is64) {
        const int4* src4 = (const int4*)w;
        const int4* dst4 = (const int4*)(w + 2 * E);
        int4 sv = src4[idx];
        int4 dv = dst4[idx];
        s0 = sv.x; d0 = dv.x; s1 = sv.z; d1 = dv.z;
    } else {
        const int2* src2 = (const int2*)w;
        const int2* dst2 = (const int2*)(w + E);
        int2 sv = src2[idx];
        int2 dv = dst2[idx];
        s0 = sv.x; d0 = dv.x; s1 = sv.y; d1 = dv.y;
    }
    if (two) {
        int2 rk = *(const int2*)&g_rank[e0];
        g_col[g_rowptr[clampi(d0, Nn)] + rk.x] = clampi(s0, Nn);
        g_col[g_rowptr[clampi(d1, Nn)] + rk.y] = clampi(s1, Nn);
    } else {
        g_col[g_rowptr[clampi(d0, Nn)] + g_rank[e0]] = clampi(s0, Nn);
    }
}

// ---------------- W preconversion: fp32 -> bf16 hi/lo words ----------------

__device__ __forceinline__ unsigned pack_bf16_hi(float2 v, float2& rem) {
    __nv_bfloat16 h0 = __float2bfloat16_rn(v.x);
    __nv_bfloat16 h1 = __float2bfloat16_rn(v.y);
    rem.x = v.x - __bfloat162float(h0);
    rem.y = v.y - __bfloat162float(h1);
    __nv_bfloat162 p = __nv_bfloat162(h0, h1);
    return *reinterpret_cast<unsigned*>(&p);
}
__device__ __forceinline__ unsigned pack_bf16(float2 v) {
    __nv_bfloat162 p = __nv_bfloat162(__float2bfloat16_rn(v.x), __float2bfloat16_rn(v.y));
    return *reinterpret_cast<unsigned*>(&p);
}

__global__ void wconv_kernel(const float* __restrict__ W1,
                             const float* __restrict__ W2,
                             const float* __restrict__ W3) {
    int idx = blockIdx.x * blockDim.x + threadIdx.x;   // 3 * 8192 words
    if (idx >= 3 * 8192) return;
    int l = idx >> 13;
    int t = idx & 8191;                                // word: row r=t>>6, w=t&63
    const float* W = (l == 0) ? W1 : (l == 1) ? W2 : W3;
    float2 v = *(const float2*)&W[2 * t];
    float2 rem;
    g_Wh[l][t] = pack_bf16_hi(v, rem);
    g_Wl[l][t] = pack_bf16(rem);
}

// ---------------- GEMM: g_xt4/g_xth = Xin @ W^T + b ----------------
// Tensor-core mma.sync m16n8k16 bf16, hi/lo split: y = Ah*Bh + Ah*Bl + Al*Bh.
// W already bf16 hi/lo in global (g_Wh/g_Wl), loaded straight to SMEM.

__device__ __forceinline__ void mma_bf16(
    float* c, unsigned a0, unsigned a1, unsigned a2, unsigned a3,
    unsigned b0, unsigned b1)
{
    asm volatile(
        "mma.sync.aligned.m16n8k16.row.col.f32.bf16.bf16.f32 "
        "{%0,%1,%2,%3}, {%4,%5,%6,%7}, {%8,%9}, {%0,%1,%2,%3};"
        : "+f"(c[0]), "+f"(c[1]), "+f"(c[2]), "+f"(c[3])
        : "r"(a0), "r"(a1), "r"(a2), "r"(a3), "r"(b0), "r"(b1));
}

__device__ __forceinline__ int swz(int r, int w) { return r * 32 + (w ^ ((r & 7) << 2)); }

__global__ __launch_bounds__(256) void gemm_kernel(
    const float* __restrict__ Xin, int layer,
    const float* __restrict__ b, int Nn)
{
    const float* X = Xin ? Xin : (const float*)g_buf4;
    const unsigned* gWh = g_Wh[layer];
    const unsigned* gWl = g_Wl[layer];
    __shared__ unsigned sAh[64 * 32];
    __shared__ unsigned sAl[64 * 32];
    __shared__ unsigned sWh[128 * 32];
    __shared__ unsigned sWl[128 * 32];

    int tid = threadIdx.x;
    int lane = tid & 31;
    int wrp = tid >> 5;
    int wm = wrp & 3;
    int wn = wrp >> 2;
    int g = lane >> 2;
    int tq = lane & 3;
    int row0 = blockIdx.x * BM;

    float c[8][4];
    #pragma unroll
    for (int j = 0; j < 8; j++)
        #pragma unroll
        for (int q = 0; q < 4; q++) c[j][q] = 0.f;

    for (int kt = 0; kt < D; kt += BK) {
        int ktw = kt >> 1;            // word offset within W rows
        if (kt) __syncthreads();
        // X tile: convert fp32 -> bf16 hi/lo
        #pragma unroll
        for (int i = 0; i < 8; i++) {
            int idx = tid + i * 256;
            int r = idx >> 5, w = idx & 31;
            int gr = row0 + r;
            float2 v = (gr < Nn) ? *(const float2*)&X[gr * D + kt + 2 * w]
                                 : make_float2(0.f, 0.f);
            float2 rem;
            sAh[swz(r, w)] = pack_bf16_hi(v, rem);
            sAl[swz(r, w)] = pack_bf16(rem);
        }
        // W tile: straight copy of pre-packed words (uint2 = 2 words)
        #pragma unroll
        for (int i = 0; i < 8; i++) {
            int idx = tid + i * 256;          // 0..2047
            int r = idx >> 4;                 // 0..127
            int w2 = (idx & 15) << 1;         // even word
            int gwi = r * 64 + ktw + w2;
            uint2 vh = *(const uint2*)&gWh[gwi];
            uint2 vl = *(const uint2*)&gWl[gwi];
            *(uint2*)&sWh[swz(r, w2)] = vh;
            *(uint2*)&sWl[swz(r, w2)] = vl;
        }
        __syncthreads();

        #pragma unroll
        for (int ks = 0; ks < 4; ks++) {
            int ra = wm * 16 + g;
            int wa = ks * 8 + tq;
            unsigned ah0 = sAh[swz(ra, wa)];
            unsigned ah1 = sAh[swz(ra + 8, wa)];
            unsigned ah2 = sAh[swz(ra, wa + 4)];
            unsigned ah3 = sAh[swz(ra + 8, wa + 4)];
            unsigned al0 = sAl[swz(ra, wa)];
            unsigned al1 = sAl[swz(ra + 8, wa)];
            unsigned al2 = sAl[swz(ra, wa + 4)];
            unsigned al3 = sAl[swz(ra + 8, wa + 4)];
            #pragma unroll
            for (int j = 0; j < 8; j++) {
                int rb = wn * 64 + j * 8 + g;
                unsigned bh0 = sWh[swz(rb, wa)];
                unsigned bh1 = sWh[swz(rb, wa + 4)];
                unsigned bl0 = sWl[swz(rb, wa)];
                unsigned bl1 = sWl[swz(rb, wa + 4)];
                mma_bf16(c[j], ah0, ah1, ah2, ah3, bh0, bh1);
                mma_bf16(c[j], ah0, ah1, ah2, ah3, bl0, bl1);
                mma_bf16(c[j], al0, al1, al2, al3, bh0, bh1);
            }
        }
    }

    float* xtf = (float*)g_xt4;
    __half2* xth2 = (__half2*)g_xth;
    int r0a = row0 + wm * 16 + g;
    #pragma unroll
    for (int j = 0; j < 8; j++) {
        int cn = wn * 64 + j * 8 + 2 * tq;
        float bx = b[cn], by = b[cn + 1];
        float2 lo = make_float2(c[j][0] + bx, c[j][1] + by);
        float2 hi = make_float2(c[j][2] + bx, c[j][3] + by);
        if (r0a < Nn) {
            *(float2*)&xtf[r0a * D + cn] = lo;
            xth2[r0a * 64 + cn / 2] = __floats2half2_rn(lo.x, lo.y);
        }
        if (r0a + 8 < Nn) {
            *(float2*)&xtf[(r0a + 8) * D + cn] = hi;
            xth2[(r0a + 8) * 64 + cn / 2] = __floats2half2_rn(hi.x, hi.y);
        }
    }
}

// ---------------- Aggregation: out = relu(mean_in(xt[src])) + xt ----------------
// Gather fp16 mirror; accumulate pairs in fp16 (HADD2), flush to fp32 every
// 8 edges. Warp per node, 8 loads in flight.

__device__ __forceinline__ void acc_half4(float4& acc, uint2 p) {
    __half2 h01 = *reinterpret_cast<__half2*>(&p.x);
    __half2 h23 = *reinterpret_cast<__half2*>(&p.y);
    float2 f01 = __half22float2(h01);
    float2 f23 = __half22float2(h23);
    acc.x += f01.x; acc.y += f01.y; acc.z += f23.x; acc.w += f23.y;
}

__global__ __launch_bounds__(256) void agg_kernel(float4* __restrict__ Oout, int Nn)
{
    int gw = (blockIdx.x * blockDim.x + threadIdx.x) >> 5;
    int lane = threadIdx.x & 31;
    if (gw >= Nn) return;
    float4* out = Oout ? Oout : g_buf4;
    int s = g_rowptr[gw];
    int e = g_rowptr[gw + 1];
    float4 acc = make_float4(0.f, 0.f, 0.f, 0.f);
    int i = s;
    for (; i + 8 <= e; i += 8) {
        uint2 p[8];
        #pragma unroll
        for (int u = 0; u < 8; u++) p[u] = g_xth[g_col[i + u] * 32 + lane];
        __half2 h01 = __float2half2_rn(0.f);
        __half2 h23 = __float2half2_rn(0.f);
        #pragma unroll
        for (int u = 0; u < 8; u++) {
            h01 = __hadd2(h01, *reinterpret_cast<__half2*>(&p[u].x));
            h23 = __hadd2(h23, *reinterpret_cast<__half2*>(&p[u].y));
        }
        float2 f01 = __half22float2(h01);
        float2 f23 = __half22float2(h23);
        acc.x += f01.x; acc.y += f01.y; acc.z += f23.x; acc.w += f23.y;
    }
    for (; i < e; i++) {
        uint2 p = g_xth[g_col[i] * 32 + lane];
        acc_half4(acc, p);
    }
    float di = g_deginv[gw];
    float4 xv = g_xt4[gw * 32 + lane];
    float4 o;
    o.x = fmaxf(acc.x * di, 0.f) + xv.x;
    o.y = fmaxf(acc.y * di, 0.f) + xv.y;
    o.z = fmaxf(acc.z * di, 0.f) + xv.z;
    o.w = fmaxf(acc.w * di, 0.f) + xv.w;
    out[gw * 32 + lane] = o;
}

// ---------------- launch ----------------

extern "C" void kernel_launch(void* const* d_in, const int* in_sizes, int n_in,
                              void* d_out, int out_size)
{
    const float* x  = (const float*)d_in[0];
    const int*   ew = (const int*)d_in[1];     // edge_index words (int32 view)
    const float* W1 = (const float*)d_in[2];
    const float* b1 = (const float*)d_in[3];
    const float* W2 = (const float*)d_in[4];
    const float* b2 = (const float*)d_in[5];
    const float* W3 = (const float*)d_in[6];
    const float* b3 = (const float*)d_in[7];
    float4* out = (float4*)d_out;

    int Nn = in_sizes[0] / D;       // 20000
    int E  = in_sizes[1] / 2;       // 640000

    int gb_e2 = ((E + 1) / 2 + 255) / 256;
    int gb_gemm = (Nn + BM - 1) / BM;
    int gb_agg = (Nn * 32 + 255) / 256;
    int nb_scan = (Nn + 1023) / 1024;

    wconv_kernel<<<(3 * 8192 + 255) / 256, 256>>>(W1, W2, W3);
    hist_kernel<<<gb_e2, 256>>>(ew, E, Nn);
    scan1_kernel<<<nb_scan, 1024>>>(Nn);
    scan3_kernel<<<nb_scan, 1024>>>(nb_scan, Nn);
    fill_kernel<<<gb_e2, 256>>>(ew, E, Nn);

    // layer 1: x -> xt -> g_buf4
    gemm_kernel<<<gb_gemm, 256>>>(x, 0, b1, Nn);
    agg_kernel<<<gb_agg, 256>>>(nullptr, Nn);
    // layer 2: g_buf4 -> xt -> g_buf4
    gemm_kernel<<<gb_gemm, 256>>>(nullptr, 1, b2, Nn);
    agg_kernel<<<gb_agg, 256>>>(nullptr, Nn);
    // layer 3: g_buf4 -> xt -> out
    gemm_kernel<<<gb_gemm, 256>>>(nullptr, 2, b3, Nn);
    agg_kernel<<<gb_agg, 256>>>(out, Nn);
}